// round 7
// baseline (speedup 1.0000x reference)
#include <cuda_runtime.h>
#include <cuda_bf16.h>
#include <math_constants.h>

#define B_      8
#define N_      8192
#define S_      2048
#define K_      16
#define DIN_    64
#define DOUT_   128
#define BN_EPS_ 1e-5f

#define FT_     256          // FPS threads (8 warps)
#define NCH_    256          // chunks
#define CHSZ_   32           // points per chunk

// ---------------- scratch (static __device__ — no allocation allowed) ----------------
__device__ int   g_fps_idx[B_ * S_];
__device__ int   g_knn_idx[B_ * S_ * K_];
__device__ float g_h[B_ * N_ * DOUT_];   // 33.5 MB, post MLP+BN+ReLU features

// ============================================================================
// 1) FPS — one CTA per batch, 256 threads, exact pruned (QuickFPS-style).
//    Points spatially counting-sorted into 256 chunks of 32; per-chunk bbox.
//    A chunk is recomputed only if lb(c,bbox)*(1-1e-5) < chunk_pd_max; the
//    margin covers all rounding, so skips are provably bit-exact no-ops.
//    Distance math: __fsub/__fmul/__fadd rn, ((dx^2+dy^2)+dz^2) — identical
//    to the reference. Ties -> smallest ORIGINAL index (jnp.argmax).
//    Chunk key u64 = valbits<<21 | (8191-orig)<<8 | cid  (plain max works).
// ============================================================================
// dynamic smem layout (bytes):
//   [0,131072)        float4 s_sort[8192]   sorted coords
//   [131072,163840)   float  s_pd[8192]
//   [163840,196608)   u32    s_orig[8192]
//   [196608,200704)   float4 s_bmin[256]
//   [200704,204800)   float4 s_bmax[256]
//   [204800,206848)   u64    s_ckey[256]
//   [206848,210944)   float4 s_cxyz[256]
//   [210944,212992)   u32    s_hist[512]
#define FPS_SMEM_ 212992

__global__ __launch_bounds__(FT_, 1)
void fps_kernel(const float* __restrict__ coords, float* __restrict__ out_coords)
{
    extern __shared__ unsigned char dynsmem[];
    float4*             s_sort = (float4*)(dynsmem);
    float*              s_pd   = (float*)(dynsmem + 131072);
    unsigned*           s_orig = (unsigned*)(dynsmem + 163840);
    float4*             s_bmin = (float4*)(dynsmem + 196608);
    float4*             s_bmax = (float4*)(dynsmem + 200704);
    unsigned long long* s_ckey = (unsigned long long*)(dynsmem + 204800);
    float4*             s_cxyz = (float4*)(dynsmem + 206848);
    unsigned*           s_hist = (unsigned*)(dynsmem + 210944);

    __shared__ int s_list[NCH_];
    __shared__ int s_cnt[2];

    const int b    = blockIdx.x;
    const int t    = threadIdx.x;
    const int lane = t & 31;
    const int w    = t >> 5;
    const unsigned FULL = 0xffffffffu;
    const float* cb = coords + (size_t)b * N_ * 3;

    // ---------------- setup: counting sort by 8x8x8 cell ----------------
    for (int v = t; v < 512; v += FT_) s_hist[v] = 0u;
    if (t < 2) s_cnt[t] = 0;
    __syncthreads();

    unsigned cells[32];
#pragma unroll
    for (int r = 0; r < 32; r++) {
        int p = t + FT_ * r;
        float x = cb[3 * p + 0], y = cb[3 * p + 1], z = cb[3 * p + 2];
        int bx = min(max((int)floorf(x) + 4, 0), 7);
        int by = min(max((int)floorf(y) + 4, 0), 7);
        int bz = min(max((int)floorf(z) + 4, 0), 7);
        unsigned cell = (unsigned)(bx | (by << 3) | (bz << 6));
        cells[r] = cell;
        atomicAdd(&s_hist[cell], 1u);
    }
    __syncthreads();
    if (t == 0) {                       // exclusive scan (setup-only, serial ok)
        unsigned acc = 0u;
        for (int j = 0; j < 512; j++) { unsigned v = s_hist[j]; s_hist[j] = acc; acc += v; }
    }
    __syncthreads();
#pragma unroll
    for (int r = 0; r < 32; r++) {
        int p = t + FT_ * r;
        float x = cb[3 * p + 0], y = cb[3 * p + 1], z = cb[3 * p + 2];
        unsigned dst = atomicAdd(&s_hist[cells[r]], 1u);
        s_sort[dst] = make_float4(x, y, z, 0.0f);
        s_orig[dst] = (unsigned)p;
        s_pd[dst]   = 1e10f;
    }
    __syncthreads();
    {   // bbox per chunk (thread t owns chunk t); init ckey with pdmax=+inf
        float mnx = CUDART_INF_F, mny = CUDART_INF_F, mnz = CUDART_INF_F;
        float mxx = -CUDART_INF_F, mxy = -CUDART_INF_F, mxz = -CUDART_INF_F;
        for (int l = 0; l < CHSZ_; l++) {
            float4 p4 = s_sort[t * CHSZ_ + l];
            mnx = fminf(mnx, p4.x); mxx = fmaxf(mxx, p4.x);
            mny = fminf(mny, p4.y); mxy = fmaxf(mxy, p4.y);
            mnz = fminf(mnz, p4.z); mxz = fmaxf(mxz, p4.z);
        }
        s_bmin[t] = make_float4(mnx, mny, mnz, 0.0f);
        s_bmax[t] = make_float4(mxx, mxy, mxz, 0.0f);
        s_ckey[t] = (unsigned long long)0x7F800000u << 21;   // pdmax = +inf
    }
    __syncthreads();

    unsigned g = 0u;
    float4 c = make_float4(cb[0], cb[1], cb[2], 0.0f);   // start at point 0

    // ---------------- main loop ----------------
    for (int i = 0; i < S_; i++) {
        if (t == 0) {
            g_fps_idx[b * S_ + i] = (int)g;
            float* oc = out_coords + ((size_t)b * S_ + i) * 3;
            oc[0] = c.x; oc[1] = c.y; oc[2] = c.z;
        }
        if (i == S_ - 1) break;

        const int buf = i & 1;

        // ---- phase 1: chunk t pruning check ----
        float4 bmn = s_bmin[t];
        float4 bmx = s_bmax[t];
        unsigned long long k0 = s_ckey[t];
        float pdmax = __uint_as_float((unsigned)(k0 >> 21));
        float ax = fmaxf(fmaxf(__fsub_rn(bmn.x, c.x), __fsub_rn(c.x, bmx.x)), 0.0f);
        float ay = fmaxf(fmaxf(__fsub_rn(bmn.y, c.y), __fsub_rn(c.y, bmx.y)), 0.0f);
        float az = fmaxf(fmaxf(__fsub_rn(bmn.z, c.z), __fsub_rn(c.z, bmx.z)), 0.0f);
        float lb = ax * ax + ay * ay + az * az;
        bool need = !(lb * 0.99999f >= pdmax);    // skip only if provably no-op

        unsigned ball = __ballot_sync(FULL, need);
        int base = 0;
        if (lane == 0) base = atomicAdd(&s_cnt[buf], __popc(ball));
        base = __shfl_sync(FULL, base, 0);
        if (need) {
            int off = __popc(ball & ((1u << lane) - 1u));
            s_list[base + off] = t;
        }
        __syncthreads();                          // BAR1
        if (t == 0) s_cnt[buf ^ 1] = 0;           // reset next-iter counter
        const int F = s_cnt[buf];

        // ---- phase 2: recompute flagged chunks (warp per chunk, strided) ----
        for (int e = w; e < F; e += FT_ / 32) {
            int cid = s_list[e];
            int sp  = cid * CHSZ_ + lane;
            float4 pt = s_sort[sp];
            float pdv = s_pd[sp];
            unsigned og = s_orig[sp];
            float dx = __fsub_rn(pt.x, c.x);
            float dy = __fsub_rn(pt.y, c.y);
            float dz = __fsub_rn(pt.z, c.z);
            float dd = __fadd_rn(__fadd_rn(__fmul_rn(dx, dx), __fmul_rn(dy, dy)),
                                 __fmul_rn(dz, dz));
            pdv = fminf(pdv, dd);
            s_pd[sp] = pdv;
            unsigned pb = __float_as_uint(pdv);           // pd >= 0: bits ordered
            unsigned wm = __reduce_max_sync(FULL, pb);
            unsigned cand = (pb == wm) ? og : 0xffffffffu;
            unsigned om = __reduce_min_sync(FULL, cand);  // min ORIGINAL index
            if (pb == wm && og == om) {
                s_ckey[cid] = ((unsigned long long)wm << 21) |
                              ((unsigned long long)(8191u - om) << 8) |
                              (unsigned long long)cid;
                s_cxyz[cid] = pt;
            }
        }
        __syncthreads();                          // BAR2

        // ---- reduce 256 chunk keys (all warps, butterfly -> all threads) ----
        unsigned long long kb = 0ull;
#pragma unroll
        for (int r = 0; r < 8; r++) {
            unsigned long long k = s_ckey[lane + 32 * r];
            if (k > kb) kb = k;
        }
#pragma unroll
        for (int off = 16; off > 0; off >>= 1) {
            unsigned long long ko = __shfl_xor_sync(FULL, kb, off);
            if (ko > kb) kb = ko;
        }
        g = 8191u - ((unsigned)(kb >> 8) & 8191u);
        c = s_cxyz[(int)(kb & 255u)];
    }
}

// ============================================================================
// 2) KNN: K=16 smallest (d, idx) lexicographic (matches top_k(-d)).
// ============================================================================
__global__ __launch_bounds__(128)
void knn_kernel(const float* __restrict__ coords)
{
    const int b = blockIdx.y;
    const int s = blockIdx.x * 128 + threadIdx.x;
    const float* cb = coords + (size_t)b * N_ * 3;

    const int qi = g_fps_idx[b * S_ + s];
    const float qx = cb[qi * 3 + 0];
    const float qy = cb[qi * 3 + 1];
    const float qz = cb[qi * 3 + 2];

    __shared__ float4 tile[2048];     // 32 KB, padded xyz

    float dk[K_];
    int   ik[K_];
#pragma unroll
    for (int j = 0; j < K_; j++) { dk[j] = CUDART_INF_F; ik[j] = 0; }

    for (int t0 = 0; t0 < N_; t0 += 2048) {
        __syncthreads();
        for (int v = threadIdx.x; v < 2048; v += 128) {
            int p = t0 + v;
            tile[v] = make_float4(cb[p * 3 + 0], cb[p * 3 + 1], cb[p * 3 + 2], 0.0f);
        }
        __syncthreads();

#pragma unroll 8
        for (int p = 0; p < 2048; p++) {
            float4 cc = tile[p];
            float dx = __fsub_rn(qx, cc.x);
            float dy = __fsub_rn(qy, cc.y);
            float dz = __fsub_rn(qz, cc.z);
            float dd = __fadd_rn(__fadd_rn(__fmul_rn(dx, dx), __fmul_rn(dy, dy)),
                                 __fmul_rn(dz, dz));
            if (dd < dk[K_ - 1]) {
                float vd = dd; int vi = t0 + p;
#pragma unroll
                for (int j = 0; j < K_; j++) {
                    if (vd < dk[j]) {
                        float td = dk[j]; int ti2 = ik[j];
                        dk[j] = vd; ik[j] = vi;
                        vd = td; vi = ti2;
                    }
                }
            }
        }
    }

    int* out = &g_knn_idx[((size_t)b * S_ + s) * K_];
#pragma unroll
    for (int j = 0; j < K_; j++) out[j] = ik[j];
}

// ============================================================================
// 3) Pointwise MLP (64->128) + BN(eval) + ReLU on ALL points -> g_h.
// ============================================================================
__global__ __launch_bounds__(256)
void mlp_kernel(const float* __restrict__ features,
                const float* __restrict__ W,
                const float* __restrict__ bias,
                const float* __restrict__ gamma,
                const float* __restrict__ beta,
                const float* __restrict__ rmean,
                const float* __restrict__ rvar)
{
    const int pt0  = blockIdx.x * 32;
    const int o    = threadIdx.x & 127;
    const int half = threadIdx.x >> 7;

    __shared__ float sW[DOUT_ * DIN_];          // 32 KB
    __shared__ float sF[32 * DIN_];             // 8 KB

    for (int v = threadIdx.x; v < DOUT_ * DIN_; v += 256) sW[v] = W[v];
    for (int v = threadIdx.x; v < 32 * DIN_;   v += 256) sF[v] = features[(size_t)pt0 * DIN_ + v];
    __syncthreads();

    float w[DIN_];
#pragma unroll
    for (int d = 0; d < DIN_; d++) w[d] = sW[o * DIN_ + d];

    const float bo = bias[o];
    const float mn = rmean[o];
    const float sc = gamma[o] * rsqrtf(rvar[o] + BN_EPS_);
    const float bt = beta[o];

    for (int p = half * 16; p < half * 16 + 16; p++) {
        float acc = 0.0f;
#pragma unroll
        for (int d = 0; d < DIN_; d += 4) {
            float4 f = *(const float4*)&sF[p * DIN_ + d];
            acc = fmaf(w[d + 0], f.x, acc);
            acc = fmaf(w[d + 1], f.y, acc);
            acc = fmaf(w[d + 2], f.z, acc);
            acc = fmaf(w[d + 3], f.w, acc);
        }
        float lin = acc + bo;
        float val = (lin - mn) * sc + bt;
        g_h[((size_t)pt0 + p) * DOUT_ + o] = fmaxf(val, 0.0f);
    }
}

// ============================================================================
// 4) Gather K neighbors' features + max-pool.
// ============================================================================
__global__ __launch_bounds__(256)
void pool_kernel(float* __restrict__ out_feat)
{
    const int b   = blockIdx.y;
    const int s   = blockIdx.x * 8 + (threadIdx.x >> 5);
    const int col = threadIdx.x & 31;

    const int* kid = &g_knn_idx[((size_t)b * S_ + s) * K_];

    float4 acc = make_float4(-CUDART_INF_F, -CUDART_INF_F, -CUDART_INF_F, -CUDART_INF_F);
#pragma unroll
    for (int k = 0; k < K_; k++) {
        const int id = kid[k];
        const float4 v = *(const float4*)&g_h[((size_t)b * N_ + id) * DOUT_ + col * 4];
        acc.x = fmaxf(acc.x, v.x);
        acc.y = fmaxf(acc.y, v.y);
        acc.z = fmaxf(acc.z, v.z);
        acc.w = fmaxf(acc.w, v.w);
    }
    *(float4*)&out_feat[((size_t)b * S_ + s) * DOUT_ + col * 4] = acc;
}

// ============================================================================
extern "C" void kernel_launch(void* const* d_in, const int* in_sizes, int n_in,
                              void* d_out, int out_size)
{
    const float* coords   = (const float*)d_in[0];
    const float* features = (const float*)d_in[1];
    const float* W        = (const float*)d_in[2];
    const float* bias     = (const float*)d_in[3];
    const float* gamma    = (const float*)d_in[4];
    const float* beta     = (const float*)d_in[5];
    const float* rmean    = (const float*)d_in[6];
    const float* rvar     = (const float*)d_in[7];

    float* out        = (float*)d_out;
    float* out_coords = out;                       // [B, S, 3]
    float* out_feat   = out + (size_t)B_ * S_ * 3; // [B, S, 128]

    static bool attr_done = false;
    if (!attr_done) {
        cudaFuncSetAttribute(fps_kernel, cudaFuncAttributeMaxDynamicSharedMemorySize,
                             FPS_SMEM_);
        attr_done = true;
    }

    fps_kernel<<<B_, FT_, FPS_SMEM_>>>(coords, out_coords);
    mlp_kernel<<<(B_ * N_) / 32, 256>>>(features, W, bias, gamma, beta, rmean, rvar);
    knn_kernel<<<dim3(S_ / 128, B_), 128>>>(coords);
    pool_kernel<<<dim3(S_ / 8, B_), 256>>>(out_feat);
}

// round 8
// speedup vs baseline: 1.3015x; 1.3015x over previous
#include <cuda_runtime.h>
#include <cuda_bf16.h>
#include <math_constants.h>

#define B_      8
#define N_      8192
#define S_      2048
#define K_      16
#define DIN_    64
#define DOUT_   128
#define BN_EPS_ 1e-5f

#define FT_     1024           // FPS threads (32 warps)
#define PPT_    8              // points per thread

// ---------------- scratch (static __device__ — no allocation allowed) ----------------
__device__ int   g_fps_idx[B_ * S_];
__device__ int   g_knn_idx[B_ * S_ * K_];
__device__ float g_h[B_ * N_ * DOUT_];   // 33.5 MB, post MLP+BN+ReLU features

// ============================================================================
// 1) FPS — one CTA per batch, 1024 threads, exact per-thread pruning.
//    Setup: counting sort by 8x8x8 cell -> thread t owns 8 spatially-adjacent
//    points (sorted positions 8t..8t+7, coords+orig packed in smem float4),
//    per-thread register bbox.
//    Iteration (round-3 skeleton, ONE barrier, double-buffered slots):
//      - bound check: if lb(c,bbox)*0.99999 >= m (cached max pd), the update
//        is provably a bit-exact no-op -> reuse cached (m, mi).
//      - else recompute 8 pds (exact IEEE __fsub/__fmul/__fadd, ((x+y)+z))
//        and local argmax with ORIGINAL-index tie-break.
//      - warp REDUX (max val bits / min orig on ties); fully-skipped warps
//        reuse the cached warp key and skip the REDUXes.
//      - BAR; every warp reduces the 32 slots; winner coords via s_pos+s_sort.
//    Ties -> smallest original index everywhere == jnp.argmax semantics.
// ============================================================================
extern __shared__ unsigned char fps_dyn[];   // s_sort[8192] float4 | s_pos[8192] u32

__global__ __launch_bounds__(FT_, 1)
void fps_kernel(const float* __restrict__ coords, float* __restrict__ out_coords)
{
    float4*   s_sort = (float4*)fps_dyn;                 // 131072 B
    unsigned* s_pos  = (unsigned*)(fps_dyn + 131072);    // 32768 B

    __shared__ unsigned s_hist[512];
    __shared__ unsigned s_wsum[16];
    __shared__ unsigned s_val[2][32];
    __shared__ unsigned s_idx[2][32];

    const int b    = blockIdx.x;
    const int t    = threadIdx.x;
    const int lane = t & 31;
    const int w    = t >> 5;
    const unsigned FULL = 0xffffffffu;
    const float* cb = coords + (size_t)b * N_ * 3;

    // ---------------- setup: counting sort by cell ----------------
    if (t < 512) s_hist[t] = 0u;
    __syncthreads();

    float f[24];
    unsigned cells[PPT_];
    {
        const float4* src = (const float4*)(cb + t * 24);   // points 8t..8t+7
#pragma unroll
        for (int q = 0; q < 6; q++) {
            float4 v = src[q];
            f[q * 4 + 0] = v.x; f[q * 4 + 1] = v.y; f[q * 4 + 2] = v.z; f[q * 4 + 3] = v.w;
        }
#pragma unroll
        for (int j = 0; j < PPT_; j++) {
            int bx = min(max((int)floorf(f[3 * j + 0]) + 4, 0), 7);
            int by = min(max((int)floorf(f[3 * j + 1]) + 4, 0), 7);
            int bz = min(max((int)floorf(f[3 * j + 2]) + 4, 0), 7);
            cells[j] = (unsigned)(bx | (by << 3) | (bz << 6));
            atomicAdd(&s_hist[cells[j]], 1u);
        }
    }
    __syncthreads();
    // parallel exclusive scan of 512 counters
    if (t < 512) {
        unsigned v = s_hist[t];
        unsigned inc = v;
#pragma unroll
        for (int off = 1; off < 32; off <<= 1) {
            unsigned u = __shfl_up_sync(FULL, inc, off);
            if (lane >= off) inc += u;
        }
        s_hist[t] = inc - v;
        if (lane == 31) s_wsum[w] = inc;
    }
    __syncthreads();
    if (t < 32) {
        unsigned v = (t < 16) ? s_wsum[t] : 0u;
        unsigned inc = v;
#pragma unroll
        for (int off = 1; off < 16; off <<= 1) {
            unsigned u = __shfl_up_sync(FULL, inc, off);
            if (lane >= off) inc += u;
        }
        if (t < 16) s_wsum[t] = inc - v;
    }
    __syncthreads();
    if (t < 512) s_hist[t] += s_wsum[t >> 5];
    __syncthreads();
    // scatter (stable order not required)
#pragma unroll
    for (int j = 0; j < PPT_; j++) {
        unsigned dst = atomicAdd(&s_hist[cells[j]], 1u);
        unsigned orig = (unsigned)(t * PPT_ + j);
        s_sort[dst] = make_float4(f[3 * j], f[3 * j + 1], f[3 * j + 2],
                                  __uint_as_float(orig));
        s_pos[orig] = dst;
    }
    __syncthreads();

    // per-thread bbox over owned sorted points + per-thread pd registers
    float pd[PPT_];
    float bmnx = CUDART_INF_F, bmny = CUDART_INF_F, bmnz = CUDART_INF_F;
    float bmxx = -CUDART_INF_F, bmxy = -CUDART_INF_F, bmxz = -CUDART_INF_F;
    {
        const int base = t * PPT_;
#pragma unroll
        for (int j = 0; j < PPT_; j++) {
            float4 p4 = s_sort[base + j];
            bmnx = fminf(bmnx, p4.x); bmxx = fmaxf(bmxx, p4.x);
            bmny = fminf(bmny, p4.y); bmxy = fmaxf(bmxy, p4.y);
            bmnz = fminf(bmnz, p4.z); bmxz = fmaxf(bmxz, p4.z);
            pd[j] = 1e10f;
        }
    }

    float    m  = CUDART_INF_F;        // cached max_j pd[j] (forces 1st compute)
    unsigned mi = 0xffffffffu;         // cached argmax original index
    unsigned wm_c = 0u, wmi_c = 0xffffffffu;   // cached warp key

    unsigned g = 0u;
    float4 c = s_sort[s_pos[0]];       // start centroid = point 0

    for (int i = 0; i < S_; i++) {
        if (t == 0) {
            g_fps_idx[b * S_ + i] = (int)g;
            float* oc = out_coords + ((size_t)b * S_ + i) * 3;
            oc[0] = c.x; oc[1] = c.y; oc[2] = c.z;
        }
        if (i == S_ - 1) break;
        const int buf = i & 1;

        // ---- bound check: skip iff provably a no-op (margin covers rounding)
        float ax = fmaxf(fmaxf(__fsub_rn(bmnx, c.x), __fsub_rn(c.x, bmxx)), 0.0f);
        float ay = fmaxf(fmaxf(__fsub_rn(bmny, c.y), __fsub_rn(c.y, bmxy)), 0.0f);
        float az = fmaxf(fmaxf(__fsub_rn(bmnz, c.z), __fsub_rn(c.z, bmxz)), 0.0f);
        float lb = ax * ax + ay * ay + az * az;
        bool need = !(lb * 0.99999f >= m);

        unsigned wm, wmi;
        unsigned bal = __ballot_sync(FULL, need);
        if (bal != 0u) {
            if (need) {
                const int base = t * PPT_;
                float nm = -CUDART_INF_F; unsigned nmi = 0xffffffffu;
#pragma unroll
                for (int j = 0; j < PPT_; j++) {
                    float4 p4 = s_sort[base + j];
                    float dx = __fsub_rn(p4.x, c.x);
                    float dy = __fsub_rn(p4.y, c.y);
                    float dz = __fsub_rn(p4.z, c.z);
                    float dd = __fadd_rn(__fadd_rn(__fmul_rn(dx, dx), __fmul_rn(dy, dy)),
                                         __fmul_rn(dz, dz));
                    float pdj = fminf(pd[j], dd);
                    pd[j] = pdj;
                    unsigned og = __float_as_uint(p4.w);
                    if (pdj > nm || (pdj == nm && og < nmi)) { nm = pdj; nmi = og; }
                }
                m = nm; mi = nmi;
            }
            // warp argmax over merged (cached or fresh) keys
            unsigned mb = __float_as_uint(m);        // pd >= 0: bits ordered
            wm = __reduce_max_sync(FULL, mb);
            unsigned cand = (mb == wm) ? mi : 0xffffffffu;
            wmi = __reduce_min_sync(FULL, cand);     // min ORIGINAL index
            wm_c = wm; wmi_c = wmi;
        } else {
            wm = wm_c; wmi = wmi_c;                  // whole warp unchanged
        }
        if (lane == 0) { s_val[buf][w] = wm; s_idx[buf][w] = wmi; }
        __syncthreads();

        // every warp reduces the 32 slots itself (no 2nd barrier)
        unsigned v  = s_val[buf][lane];
        unsigned ix = s_idx[buf][lane];
        unsigned gm = __reduce_max_sync(FULL, v);
        unsigned c2 = (v == gm) ? ix : 0xffffffffu;
        g = __reduce_min_sync(FULL, c2);
        c = s_sort[s_pos[g]];                        // broadcast LDS
    }
}

// ============================================================================
// 2) KNN: K=16 smallest (d, idx) lexicographic (matches top_k(-d)).
// ============================================================================
__global__ __launch_bounds__(128)
void knn_kernel(const float* __restrict__ coords)
{
    const int b = blockIdx.y;
    const int s = blockIdx.x * 128 + threadIdx.x;
    const float* cb = coords + (size_t)b * N_ * 3;

    const int qi = g_fps_idx[b * S_ + s];
    const float qx = cb[qi * 3 + 0];
    const float qy = cb[qi * 3 + 1];
    const float qz = cb[qi * 3 + 2];

    __shared__ float4 tile[2048];     // 32 KB, padded xyz

    float dk[K_];
    int   ik[K_];
#pragma unroll
    for (int j = 0; j < K_; j++) { dk[j] = CUDART_INF_F; ik[j] = 0; }

    for (int t0 = 0; t0 < N_; t0 += 2048) {
        __syncthreads();
        for (int v = threadIdx.x; v < 2048; v += 128) {
            int p = t0 + v;
            tile[v] = make_float4(cb[p * 3 + 0], cb[p * 3 + 1], cb[p * 3 + 2], 0.0f);
        }
        __syncthreads();

#pragma unroll 8
        for (int p = 0; p < 2048; p++) {
            float4 cc = tile[p];
            float dx = __fsub_rn(qx, cc.x);
            float dy = __fsub_rn(qy, cc.y);
            float dz = __fsub_rn(qz, cc.z);
            float dd = __fadd_rn(__fadd_rn(__fmul_rn(dx, dx), __fmul_rn(dy, dy)),
                                 __fmul_rn(dz, dz));
            if (dd < dk[K_ - 1]) {
                float vd = dd; int vi = t0 + p;
#pragma unroll
                for (int j = 0; j < K_; j++) {
                    if (vd < dk[j]) {
                        float td = dk[j]; int ti2 = ik[j];
                        dk[j] = vd; ik[j] = vi;
                        vd = td; vi = ti2;
                    }
                }
            }
        }
    }

    int* out = &g_knn_idx[((size_t)b * S_ + s) * K_];
#pragma unroll
    for (int j = 0; j < K_; j++) out[j] = ik[j];
}

// ============================================================================
// 3) Pointwise MLP (64->128) + BN(eval) + ReLU on ALL points -> g_h.
// ============================================================================
__global__ __launch_bounds__(256)
void mlp_kernel(const float* __restrict__ features,
                const float* __restrict__ W,
                const float* __restrict__ bias,
                const float* __restrict__ gamma,
                const float* __restrict__ beta,
                const float* __restrict__ rmean,
                const float* __restrict__ rvar)
{
    const int pt0  = blockIdx.x * 32;
    const int o    = threadIdx.x & 127;
    const int half = threadIdx.x >> 7;

    __shared__ float sW[DOUT_ * DIN_];          // 32 KB
    __shared__ float sF[32 * DIN_];             // 8 KB

    for (int v = threadIdx.x; v < DOUT_ * DIN_; v += 256) sW[v] = W[v];
    for (int v = threadIdx.x; v < 32 * DIN_;   v += 256) sF[v] = features[(size_t)pt0 * DIN_ + v];
    __syncthreads();

    float w[DIN_];
#pragma unroll
    for (int d = 0; d < DIN_; d++) w[d] = sW[o * DIN_ + d];

    const float bo = bias[o];
    const float mn = rmean[o];
    const float sc = gamma[o] * rsqrtf(rvar[o] + BN_EPS_);
    const float bt = beta[o];

    for (int p = half * 16; p < half * 16 + 16; p++) {
        float acc = 0.0f;
#pragma unroll
        for (int d = 0; d < DIN_; d += 4) {
            float4 ff = *(const float4*)&sF[p * DIN_ + d];
            acc = fmaf(w[d + 0], ff.x, acc);
            acc = fmaf(w[d + 1], ff.y, acc);
            acc = fmaf(w[d + 2], ff.z, acc);
            acc = fmaf(w[d + 3], ff.w, acc);
        }
        float lin = acc + bo;
        float val = (lin - mn) * sc + bt;
        g_h[((size_t)pt0 + p) * DOUT_ + o] = fmaxf(val, 0.0f);
    }
}

// ============================================================================
// 4) Gather K neighbors' features + max-pool.
// ============================================================================
__global__ __launch_bounds__(256)
void pool_kernel(float* __restrict__ out_feat)
{
    const int b   = blockIdx.y;
    const int s   = blockIdx.x * 8 + (threadIdx.x >> 5);
    const int col = threadIdx.x & 31;

    const int* kid = &g_knn_idx[((size_t)b * S_ + s) * K_];

    float4 acc = make_float4(-CUDART_INF_F, -CUDART_INF_F, -CUDART_INF_F, -CUDART_INF_F);
#pragma unroll
    for (int k = 0; k < K_; k++) {
        const int id = kid[k];
        const float4 v = *(const float4*)&g_h[((size_t)b * N_ + id) * DOUT_ + col * 4];
        acc.x = fmaxf(acc.x, v.x);
        acc.y = fmaxf(acc.y, v.y);
        acc.z = fmaxf(acc.z, v.z);
        acc.w = fmaxf(acc.w, v.w);
    }
    *(float4*)&out_feat[((size_t)b * S_ + s) * DOUT_ + col * 4] = acc;
}

// ============================================================================
extern "C" void kernel_launch(void* const* d_in, const int* in_sizes, int n_in,
                              void* d_out, int out_size)
{
    const float* coords   = (const float*)d_in[0];
    const float* features = (const float*)d_in[1];
    const float* W        = (const float*)d_in[2];
    const float* bias     = (const float*)d_in[3];
    const float* gamma    = (const float*)d_in[4];
    const float* beta     = (const float*)d_in[5];
    const float* rmean    = (const float*)d_in[6];
    const float* rvar     = (const float*)d_in[7];

    float* out        = (float*)d_out;
    float* out_coords = out;                       // [B, S, 3]
    float* out_feat   = out + (size_t)B_ * S_ * 3; // [B, S, 128]

    const int fps_dyn_bytes = N_ * (int)sizeof(float4) + N_ * (int)sizeof(unsigned);
    static bool attr_done = false;
    if (!attr_done) {
        cudaFuncSetAttribute(fps_kernel, cudaFuncAttributeMaxDynamicSharedMemorySize,
                             fps_dyn_bytes);
        attr_done = true;
    }

    fps_kernel<<<B_, FT_, fps_dyn_bytes>>>(coords, out_coords);
    mlp_kernel<<<(B_ * N_) / 32, 256>>>(features, W, bias, gamma, beta, rmean, rvar);
    knn_kernel<<<dim3(S_ / 128, B_), 128>>>(coords);
    pool_kernel<<<dim3(S_ / 8, B_), 256>>>(out_feat);
}